// round 12
// baseline (speedup 1.0000x reference)
#include <cuda_runtime.h>
#include <cuda_bf16.h>
#include <math.h>
#include <stdint.h>

#define B_    2048
#define D_    1024
#define H_    8
#define F_    4096
#define L_    2
#define MEM_  16
#define ACT_  32
#define STO_  1024
#define HID_  1024
#define HD_   128
#define S_    17
#define BS_   (B_*S_)
#define TOKK_ 1088
#define RELW_ 513
#define SCALE_ 0.08838834764831845f
#define EPS_  1e-4f

typedef __nv_bfloat16 bf16;

// ---- scratch ----
__device__ __align__(256) float g_seq[BS_*D_];
__device__ __align__(256) bf16  g_xnh[BS_*D_];
__device__ __align__(256) bf16  g_xnl[BS_*D_];
__device__ __align__(256) float g_q[BS_*D_];
__device__ __align__(256) float g_k[BS_*D_];
__device__ __align__(256) float g_v[BS_*D_];
__device__ __align__(256) bf16  g_atth[BS_*D_];
__device__ __align__(256) bf16  g_attl[BS_*D_];
__device__ __align__(256) bf16  g_ffhh[(size_t)BS_*F_];
__device__ __align__(256) bf16  g_ffhl[(size_t)BS_*F_];
__device__ __align__(256) float g_h1[B_*HID_];
__device__ __align__(256) bf16  g_h2h[B_*HID_];
__device__ __align__(256) bf16  g_h2l[B_*HID_];
__device__ __align__(256) bf16  g_tokh[B_*TOKK_];
__device__ __align__(256) bf16  g_tokl[B_*TOKK_];

#define SZ_SQ   (1024ull*1024ull)
#define OFF_W1T 0ull
#define SZ_W1T  (1024ull*1088ull)
#define OFF_W2T (OFF_W1T + SZ_W1T)
#define OFF_LYR(l) (OFF_W2T + SZ_SQ + (unsigned long long)(l)*12ull*SZ_SQ)
#define OFF_Q(l)  (OFF_LYR(l))
#define OFF_K(l)  (OFF_LYR(l) + 1ull*SZ_SQ)
#define OFF_V(l)  (OFF_LYR(l) + 2ull*SZ_SQ)
#define OFF_O(l)  (OFF_LYR(l) + 3ull*SZ_SQ)
#define OFF_F1(l) (OFF_LYR(l) + 4ull*SZ_SQ)
#define OFF_F2(l) (OFF_LYR(l) + 8ull*SZ_SQ)
#define WT_TOTAL  (OFF_W2T + SZ_SQ + 2ull*12ull*SZ_SQ)
__device__ __align__(256) bf16 g_wth[WT_TOTAL];
__device__ __align__(256) bf16 g_wtl[WT_TOTAL];

// ---- helpers ----
__device__ __forceinline__ uint32_t s2u(const void* p){
    uint32_t a;
    asm("{ .reg .u64 t; cvta.to.shared.u64 t, %1; cvt.u32.u64 %0, t; }" : "=r"(a) : "l"(p));
    return a;
}
__device__ __forceinline__ void cp16(uint32_t d, const void* s){
    asm volatile("cp.async.cg.shared.global [%0], [%1], 16;" :: "r"(d), "l"(s));
}
__device__ __forceinline__ void ldsm4(uint32_t* r, uint32_t a){
    asm volatile("ldmatrix.sync.aligned.m8n8.x4.shared.b16 {%0,%1,%2,%3}, [%4];"
        : "=r"(r[0]),"=r"(r[1]),"=r"(r[2]),"=r"(r[3]) : "r"(a));
}
__device__ __forceinline__ void mma16816(float* d, const uint32_t* a, const uint32_t* b){
    asm volatile("mma.sync.aligned.m16n8k16.row.col.f32.bf16.bf16.f32 "
        "{%0,%1,%2,%3}, {%4,%5,%6,%7}, {%8,%9}, {%0,%1,%2,%3};"
        : "+f"(d[0]),"+f"(d[1]),"+f"(d[2]),"+f"(d[3])
        : "r"(a[0]),"r"(a[1]),"r"(a[2]),"r"(a[3]), "r"(b[0]),"r"(b[1]));
}
__device__ __forceinline__ float gelu_exact(float x){
    return 0.5f * x * (1.0f + erff(x * 0.70710678118654752f));
}
__device__ __forceinline__ void split_bf16(float v, bf16& h, bf16& l){
    h = __float2bfloat16_rn(v);
    l = __float2bfloat16_rn(v - __bfloat162float(h));
}

// ---- GEMM: C[M,N] = (Ahi+Alo)[M,K] @ (Bhi+Blo)[N,K]^T + bias; mma.sync bf16 3-pass ----
// EPI: 0 bias->Cf; 1 bias+gelu->Chi/Clo; 2 bias+residual(Cf)->Cf
// Stage: K=32. Tiles 128rows x 32cols bf16, padded row stride 80B. 4 tiles/stage = 40960B.
#define STG_B   40960
#define GEMM_SMEM (4*STG_B)

template<int EPI>
__global__ void __launch_bounds__(256, 1) gemm_bf16x3(
    const bf16* __restrict__ Ahi, const bf16* __restrict__ Alo,
    const bf16* __restrict__ Bhi, const bf16* __restrict__ Blo,
    const float* __restrict__ bias, float* __restrict__ Cf,
    bf16* __restrict__ Chi, bf16* __restrict__ Clo,
    int N, int K, int nstages)
{
    extern __shared__ __align__(128) char sm_[];
    uint32_t sb = s2u(sm_);
    const int tid = threadIdx.x;
    const int wid = tid >> 5, lane = tid & 31;
    const int warp_m = wid & 3, warp_n = wid >> 2;     // 4 x 2 warps
    const int m0 = blockIdx.y * 128, n0 = blockIdx.x * 128;

    const size_t rowK = (size_t)K * 2;                  // row stride bytes
    const char* pAh = (const char*)Ahi + (size_t)m0 * rowK;
    const char* pAl = (const char*)Alo + (size_t)m0 * rowK;
    const char* pBh = (const char*)Bhi + (size_t)n0 * rowK;
    const char* pBl = (const char*)Blo + (size_t)n0 * rowK;

    auto load_stage = [&](int ks, int buf){
        uint32_t base = sb + buf * STG_B;
        size_t kb = (size_t)ks * 64;                    // 32 bf16 = 64 bytes
        #pragma unroll
        for (int t = 0; t < 2; t++){
            int idx = tid + t * 256;                    // 0..511
            int r = idx >> 2, c = idx & 3;
            uint32_t doff = r * 80 + c * 16;
            size_t go = (size_t)r * rowK + kb + c * 16;
            cp16(base + doff,         pAh + go);
            cp16(base + 10240 + doff, pAl + go);
            cp16(base + 20480 + doff, pBh + go);
            cp16(base + 30720 + doff, pBl + go);
        }
        asm volatile("cp.async.commit_group;" ::: "memory");
    };

    int npro = nstages < 3 ? nstages : 3;
    for (int i = 0; i < npro; i++) load_stage(i, i);

    float acc[2][8][4];
    #pragma unroll
    for (int mt = 0; mt < 2; mt++)
        #pragma unroll
        for (int nf = 0; nf < 8; nf++)
            #pragma unroll
            for (int i = 0; i < 4; i++) acc[mt][nf][i] = 0.f;

    const uint32_t aoff = (warp_m * 32 + (lane & 15)) * 80 + (lane >> 4) * 16;
    const uint32_t boff = (warp_n * 64 + (lane & 15)) * 80 + ((lane >> 4) & 1) * 16;

    for (int s = 0; s < nstages; s++){
        int rem = nstages - 1 - s;
        if (rem >= 2)      asm volatile("cp.async.wait_group 2;" ::: "memory");
        else if (rem == 1) asm volatile("cp.async.wait_group 1;" ::: "memory");
        else               asm volatile("cp.async.wait_group 0;" ::: "memory");
        __syncthreads();
        if (s + 3 < nstages) load_stage(s + 3, (s + 3) & 3);

        uint32_t base = sb + (s & 3) * STG_B;
        #pragma unroll
        for (int ks = 0; ks < 2; ks++){
            uint32_t ah[2][4], al[2][4], bh[8][2], bl[8][2];
            #pragma unroll
            for (int mt = 0; mt < 2; mt++){
                uint32_t ra = base + aoff + mt * (16 * 80) + ks * 32;
                ldsm4(ah[mt], ra);
                ldsm4(al[mt], ra + 10240);
            }
            #pragma unroll
            for (int fp = 0; fp < 4; fp++){
                uint32_t rb = base + 20480 + boff + fp * (16 * 80) + ks * 32;
                uint32_t tt[4];
                ldsm4(tt, rb);
                bh[2*fp][0] = tt[0]; bh[2*fp+1][0] = tt[1];
                bh[2*fp][1] = tt[2]; bh[2*fp+1][1] = tt[3];
                ldsm4(tt, rb + 10240);
                bl[2*fp][0] = tt[0]; bl[2*fp+1][0] = tt[1];
                bl[2*fp][1] = tt[2]; bl[2*fp+1][1] = tt[3];
            }
            #pragma unroll
            for (int mt = 0; mt < 2; mt++)
                #pragma unroll
                for (int nf = 0; nf < 8; nf++){
                    mma16816(acc[mt][nf], ah[mt], bh[nf]);
                    mma16816(acc[mt][nf], ah[mt], bl[nf]);
                    mma16816(acc[mt][nf], al[mt], bh[nf]);
                }
        }
    }

    // ---- epilogue ----
    const int g = lane >> 2, tig = lane & 3;
    #pragma unroll
    for (int mt = 0; mt < 2; mt++){
        int r0 = m0 + warp_m * 32 + mt * 16 + g;
        #pragma unroll
        for (int nf = 0; nf < 8; nf++){
            int j0 = n0 + warp_n * 64 + nf * 8 + 2 * tig;
            float b0 = bias[j0], b1 = bias[j0 + 1];
            float v00 = acc[mt][nf][0] + b0, v01 = acc[mt][nf][1] + b1;
            float v10 = acc[mt][nf][2] + b0, v11 = acc[mt][nf][3] + b1;
            size_t o0 = (size_t)r0 * N + j0;
            size_t o1 = (size_t)(r0 + 8) * N + j0;
            if (EPI == 0){
                float2 w0 = {v00, v01}, w1 = {v10, v11};
                *(float2*)&Cf[o0] = w0;
                *(float2*)&Cf[o1] = w1;
            } else if (EPI == 2){
                float2 r0v = *(const float2*)&Cf[o0];
                float2 r1v = *(const float2*)&Cf[o1];
                float2 w0 = {v00 + r0v.x, v01 + r0v.y};
                float2 w1 = {v10 + r1v.x, v11 + r1v.y};
                *(float2*)&Cf[o0] = w0;
                *(float2*)&Cf[o1] = w1;
            } else {
                v00 = gelu_exact(v00); v01 = gelu_exact(v01);
                v10 = gelu_exact(v10); v11 = gelu_exact(v11);
                bf16 h0,h1,h2,h3,l0,l1,l2,l3;
                split_bf16(v00,h0,l0); split_bf16(v01,h1,l1);
                split_bf16(v10,h2,l2); split_bf16(v11,h3,l3);
                *(__nv_bfloat162*)(Chi + o0) = __halves2bfloat162(h0, h1);
                *(__nv_bfloat162*)(Chi + o1) = __halves2bfloat162(h2, h3);
                *(__nv_bfloat162*)(Clo + o0) = __halves2bfloat162(l0, l1);
                *(__nv_bfloat162*)(Clo + o1) = __halves2bfloat162(l2, l3);
            }
        }
    }
}

// ---- weight transpose+split: W[K,N] f32 -> T[N,Kpad] bf16 hi/lo ----
__global__ void transpose_split(const float* __restrict__ W, bf16* __restrict__ Thi,
                                bf16* __restrict__ Tlo, int K, int N, int Kpad)
{
    __shared__ float t[32][33];
    int n0 = blockIdx.x * 32, k0 = blockIdx.y * 32;
    int tx = threadIdx.x, ty = threadIdx.y;
    #pragma unroll
    for (int i = 0; i < 4; i++){
        int k = k0 + ty + i * 8;
        t[ty + i * 8][tx] = (k < K) ? W[(size_t)k * N + n0 + tx] : 0.f;
    }
    __syncthreads();
    #pragma unroll
    for (int i = 0; i < 4; i++){
        int n = n0 + ty + i * 8;
        int k = k0 + tx;
        bf16 h, l; split_bf16(t[tx][ty + i * 8], h, l);
        Thi[(size_t)n * Kpad + k] = h;
        Tlo[(size_t)n * Kpad + k] = l;
    }
}

__global__ void build_tok(const float* __restrict__ stoch, const float* __restrict__ action,
                          bf16* __restrict__ th, bf16* __restrict__ tl)
{
    int idx = blockIdx.x * blockDim.x + threadIdx.x;
    if (idx >= B_ * TOKK_) return;
    int b = idx / TOKK_, c = idx % TOKK_;
    float v = 0.f;
    if (c < STO_) v = stoch[b * STO_ + c];
    else if (c < STO_ + ACT_){
        float a = action[b * ACT_ + (c - STO_)];
        v = a / fmaxf(fabsf(a), 1.0f);
    }
    bf16 h, l; split_bf16(v, h, l);
    th[idx] = h; tl[idx] = l;
}

__global__ void build_seq(const float* __restrict__ memory, const float* __restrict__ tok,
                          float* __restrict__ seq)
{
    int idx = blockIdx.x * blockDim.x + threadIdx.x;
    if (idx >= BS_ * D_) return;
    int b = idx / (S_ * D_);
    int r = idx % (S_ * D_);
    int s = r / D_, d = r % D_;
    seq[idx] = (s < MEM_) ? memory[((size_t)b * MEM_ + s) * D_ + d]
                          : tok[(size_t)b * D_ + d];
}

__global__ void rmsnorm_split(const float* __restrict__ x, const float* __restrict__ w,
                              bf16* __restrict__ yh, bf16* __restrict__ yl, int apply_silu)
{
    __shared__ float red[8];
    int row = blockIdx.x, tid = threadIdx.x;
    float4 v = ((const float4*)(x + (size_t)row * 1024))[tid];
    float ss = v.x*v.x + v.y*v.y + v.z*v.z + v.w*v.w;
    #pragma unroll
    for (int o = 16; o; o >>= 1) ss += __shfl_xor_sync(0xffffffffu, ss, o);
    if ((tid & 31) == 0) red[tid >> 5] = ss;
    __syncthreads();
    float tot = 0.f;
    #pragma unroll
    for (int i = 0; i < 8; i++) tot += red[i];
    float inv = rsqrtf(tot * (1.0f/1024.0f) + EPS_);
    float4 wv = ((const float4*)w)[tid];
    float o0 = v.x*inv*wv.x, o1 = v.y*inv*wv.y, o2 = v.z*inv*wv.z, o3 = v.w*inv*wv.w;
    if (apply_silu){
        o0 /= (1.f + expf(-o0)); o1 /= (1.f + expf(-o1));
        o2 /= (1.f + expf(-o2)); o3 /= (1.f + expf(-o3));
    }
    bf16 h0,h1,h2,h3,l0,l1,l2,l3;
    split_bf16(o0,h0,l0); split_bf16(o1,h1,l1);
    split_bf16(o2,h2,l2); split_bf16(o3,h3,l3);
    size_t off = (size_t)row * 1024 + tid * 4;
    *(__nv_bfloat162*)(yh + off)     = __halves2bfloat162(h0, h1);
    *(__nv_bfloat162*)(yh + off + 2) = __halves2bfloat162(h2, h3);
    *(__nv_bfloat162*)(yl + off)     = __halves2bfloat162(l0, l1);
    *(__nv_bfloat162*)(yl + off + 2) = __halves2bfloat162(l2, l3);
}

__global__ void __launch_bounds__(256) attention_kernel(
    const float* __restrict__ q, const float* __restrict__ k,
    const float* __restrict__ v, const float* __restrict__ rel_l,
    bf16* __restrict__ atth, bf16* __restrict__ attl)
{
    __shared__ __align__(16) float sv[S_][132];
    __shared__ float sq[S_][129];
    __shared__ float sk[S_][129];
    int bh = blockIdx.x;
    int b = bh >> 3, h = bh & 7;
    int tid = threadIdx.x;
    for (int idx = tid; idx < S_ * HD_; idx += 256){
        int s = idx / HD_, d = idx % HD_;
        size_t g = ((size_t)(b * S_ + s)) * D_ + h * HD_ + d;
        sq[s][d] = q[g]; sk[s][d] = k[g]; sv[s][d] = v[g];
    }
    __syncthreads();
    int warp = tid >> 5, lane = tid & 31;
    for (int qs = warp; qs < S_; qs += 8){
        float score = -1e30f;
        if (lane < S_){
            float s = 0.f;
            #pragma unroll 8
            for (int d = 0; d < HD_; d++) s += sq[qs][d] * sk[lane][d];
            score = s * SCALE_ + rel_l[(qs - lane + 256) * H_ + h];
        }
        float m = score;
        #pragma unroll
        for (int o = 16; o; o >>= 1) m = fmaxf(m, __shfl_xor_sync(0xffffffffu, m, o));
        float p = (lane < S_) ? expf(score - m) : 0.f;
        float sum = p;
        #pragma unroll
        for (int o = 16; o; o >>= 1) sum += __shfl_xor_sync(0xffffffffu, sum, o);
        p /= sum;
        float a0 = 0.f, a1 = 0.f, a2 = 0.f, a3 = 0.f;
        #pragma unroll
        for (int ks = 0; ks < S_; ks++){
            float pk = __shfl_sync(0xffffffffu, p, ks);
            float4 vv = *(const float4*)&sv[ks][lane * 4];
            a0 += pk * vv.x; a1 += pk * vv.y; a2 += pk * vv.z; a3 += pk * vv.w;
        }
        bf16 h0,h1,h2,h3,l0,l1,l2,l3;
        split_bf16(a0,h0,l0); split_bf16(a1,h1,l1);
        split_bf16(a2,h2,l2); split_bf16(a3,h3,l3);
        size_t o = ((size_t)(b * S_ + qs)) * D_ + h * HD_ + lane * 4;
        *(__nv_bfloat162*)(atth + o)     = __halves2bfloat162(h0, h1);
        *(__nv_bfloat162*)(atth + o + 2) = __halves2bfloat162(h2, h3);
        *(__nv_bfloat162*)(attl + o)     = __halves2bfloat162(l0, l1);
        *(__nv_bfloat162*)(attl + o + 2) = __halves2bfloat162(l2, l3);
    }
}

__global__ void final_deter_kernel(const float* __restrict__ seq, const float* __restrict__ deter,
                                   const float* __restrict__ fnw, float* __restrict__ out)
{
    __shared__ float red[8];
    int b = blockIdx.x, tid = threadIdx.x;
    float4 x  = ((const float4*)(seq + ((size_t)(b * S_ + S_ - 1)) * D_))[tid];
    float4 dd = ((const float4*)(deter + (size_t)b * D_))[tid];
    float4 t = {x.x + dd.x, x.y + dd.y, x.z + dd.z, x.w + dd.w};
    float ss = t.x*t.x + t.y*t.y + t.z*t.z + t.w*t.w;
    #pragma unroll
    for (int o = 16; o; o >>= 1) ss += __shfl_xor_sync(0xffffffffu, ss, o);
    if ((tid & 31) == 0) red[tid >> 5] = ss;
    __syncthreads();
    float tot = 0.f;
    #pragma unroll
    for (int i = 0; i < 8; i++) tot += red[i];
    float inv = rsqrtf(tot * (1.0f/1024.0f) + EPS_);
    float4 w = ((const float4*)fnw)[tid];
    float4 o = {t.x*inv*w.x, t.y*inv*w.y, t.z*inv*w.z, t.w*inv*w.w};
    ((float4*)(out + (size_t)b * D_))[tid] = o;
}

__global__ void copy_mem_kernel(const float* __restrict__ seq, float* __restrict__ out)
{
    int idx = blockIdx.x * blockDim.x + threadIdx.x;
    if (idx >= B_ * MEM_ * D_) return;
    int b = idx / (MEM_ * D_);
    int r = idx % (MEM_ * D_);
    out[idx] = seq[((size_t)b * S_ + 1) * D_ + r];
}

extern "C" void kernel_launch(void* const* d_in, const int* in_sizes, int n_in,
                              void* d_out, int out_size)
{
    const float* stoch   = (const float*)d_in[0];
    const float* deter   = (const float*)d_in[1];
    const float* action  = (const float*)d_in[2];
    const float* memory  = (const float*)d_in[3];
    const float* inp_w1  = (const float*)d_in[4];
    const float* inp_b1  = (const float*)d_in[5];
    const float* inp_nw  = (const float*)d_in[6];
    const float* inp_w2  = (const float*)d_in[7];
    const float* inp_b2  = (const float*)d_in[8];
    const float* Wq      = (const float*)d_in[9];
    const float* bq      = (const float*)d_in[10];
    const float* Wk      = (const float*)d_in[11];
    const float* bk      = (const float*)d_in[12];
    const float* Wv      = (const float*)d_in[13];
    const float* bv      = (const float*)d_in[14];
    const float* Wo      = (const float*)d_in[15];
    const float* bo      = (const float*)d_in[16];
    const float* rel_emb = (const float*)d_in[17];
    const float* n1w     = (const float*)d_in[18];
    const float* n2w     = (const float*)d_in[19];
    const float* ffw1    = (const float*)d_in[20];
    const float* ffb1    = (const float*)d_in[21];
    const float* ffw2    = (const float*)d_in[22];
    const float* ffb2    = (const float*)d_in[23];
    const float* fnw     = (const float*)d_in[24];
    float* out = (float*)d_out;

    float *seq, *q, *k, *v, *h1;
    bf16 *xnh, *xnl, *atth, *attl, *ffhh, *ffhl, *h2h, *h2l, *tokh, *tokl, *wth, *wtl;
    cudaGetSymbolAddress((void**)&seq,  g_seq);
    cudaGetSymbolAddress((void**)&xnh,  g_xnh);  cudaGetSymbolAddress((void**)&xnl,  g_xnl);
    cudaGetSymbolAddress((void**)&q,    g_q);    cudaGetSymbolAddress((void**)&k,    g_k);
    cudaGetSymbolAddress((void**)&v,    g_v);
    cudaGetSymbolAddress((void**)&atth, g_atth); cudaGetSymbolAddress((void**)&attl, g_attl);
    cudaGetSymbolAddress((void**)&ffhh, g_ffhh); cudaGetSymbolAddress((void**)&ffhl, g_ffhl);
    cudaGetSymbolAddress((void**)&h1,   g_h1);
    cudaGetSymbolAddress((void**)&h2h,  g_h2h);  cudaGetSymbolAddress((void**)&h2l,  g_h2l);
    cudaGetSymbolAddress((void**)&tokh, g_tokh); cudaGetSymbolAddress((void**)&tokl, g_tokl);
    cudaGetSymbolAddress((void**)&wth,  g_wth);  cudaGetSymbolAddress((void**)&wtl,  g_wtl);

    cudaFuncSetAttribute(gemm_bf16x3<0>, cudaFuncAttributeMaxDynamicSharedMemorySize, GEMM_SMEM);
    cudaFuncSetAttribute(gemm_bf16x3<1>, cudaFuncAttributeMaxDynamicSharedMemorySize, GEMM_SMEM);
    cudaFuncSetAttribute(gemm_bf16x3<2>, cudaFuncAttributeMaxDynamicSharedMemorySize, GEMM_SMEM);

    dim3 tb(32, 8);
    transpose_split<<<dim3(32, 34), tb>>>(inp_w1, wth + OFF_W1T, wtl + OFF_W1T, 1056, 1024, 1088);
    transpose_split<<<dim3(32, 32), tb>>>(inp_w2, wth + OFF_W2T, wtl + OFF_W2T, 1024, 1024, 1024);
    for (int l = 0; l < L_; l++){
        transpose_split<<<dim3(32, 32), tb>>>(Wq + (size_t)l*D_*D_,   wth + OFF_Q(l),  wtl + OFF_Q(l),  1024, 1024, 1024);
        transpose_split<<<dim3(32, 32), tb>>>(Wk + (size_t)l*D_*D_,   wth + OFF_K(l),  wtl + OFF_K(l),  1024, 1024, 1024);
        transpose_split<<<dim3(32, 32), tb>>>(Wv + (size_t)l*D_*D_,   wth + OFF_V(l),  wtl + OFF_V(l),  1024, 1024, 1024);
        transpose_split<<<dim3(32, 32), tb>>>(Wo + (size_t)l*D_*D_,   wth + OFF_O(l),  wtl + OFF_O(l),  1024, 1024, 1024);
        transpose_split<<<dim3(128, 32), tb>>>(ffw1 + (size_t)l*D_*F_, wth + OFF_F1(l), wtl + OFF_F1(l), 1024, 4096, 1024);
        transpose_split<<<dim3(32, 128), tb>>>(ffw2 + (size_t)l*F_*D_, wth + OFF_F2(l), wtl + OFF_F2(l), 4096, 1024, 4096);
    }

    build_tok<<<(B_*TOKK_ + 255)/256, 256>>>(stoch, action, tokh, tokl);
    gemm_bf16x3<0><<<dim3(8, 16), 256, GEMM_SMEM>>>(tokh, tokl, wth + OFF_W1T, wtl + OFF_W1T,
                                                    inp_b1, h1, nullptr, nullptr, 1024, 1088, 34);
    rmsnorm_split<<<B_, 256>>>(h1, inp_nw, h2h, h2l, 1);
    gemm_bf16x3<0><<<dim3(8, 16), 256, GEMM_SMEM>>>(h2h, h2l, wth + OFF_W2T, wtl + OFF_W2T,
                                                    inp_b2, h1, nullptr, nullptr, 1024, 1024, 32);
    build_seq<<<(BS_*D_ + 255)/256, 256>>>(memory, h1, seq);

    for (int l = 0; l < L_; l++){
        rmsnorm_split<<<BS_, 256>>>(seq, n1w + l*D_, xnh, xnl, 0);
        gemm_bf16x3<0><<<dim3(8, 272), 256, GEMM_SMEM>>>(xnh, xnl, wth + OFF_Q(l), wtl + OFF_Q(l),
                                                         bq + l*D_, q, nullptr, nullptr, 1024, 1024, 32);
        gemm_bf16x3<0><<<dim3(8, 272), 256, GEMM_SMEM>>>(xnh, xnl, wth + OFF_K(l), wtl + OFF_K(l),
                                                         bk + l*D_, k, nullptr, nullptr, 1024, 1024, 32);
        gemm_bf16x3<0><<<dim3(8, 272), 256, GEMM_SMEM>>>(xnh, xnl, wth + OFF_V(l), wtl + OFF_V(l),
                                                         bv + l*D_, v, nullptr, nullptr, 1024, 1024, 32);
        attention_kernel<<<B_*H_, 256>>>(q, k, v, rel_emb + (size_t)l*RELW_*H_, atth, attl);
        gemm_bf16x3<2><<<dim3(8, 272), 256, GEMM_SMEM>>>(atth, attl, wth + OFF_O(l), wtl + OFF_O(l),
                                                         bo + l*D_, seq, nullptr, nullptr, 1024, 1024, 32);
        rmsnorm_split<<<BS_, 256>>>(seq, n2w + l*D_, xnh, xnl, 0);
        gemm_bf16x3<1><<<dim3(32, 272), 256, GEMM_SMEM>>>(xnh, xnl, wth + OFF_F1(l), wtl + OFF_F1(l),
                                                          ffb1 + l*F_, nullptr, ffhh, ffhl, 4096, 1024, 32);
        gemm_bf16x3<2><<<dim3(8, 272), 256, GEMM_SMEM>>>(ffhh, ffhl, wth + OFF_F2(l), wtl + OFF_F2(l),
                                                         ffb2 + l*D_, seq, nullptr, nullptr, 1024, 4096, 128);
    }

    final_deter_kernel<<<B_, 256>>>(seq, deter, fnw, out);
    copy_mem_kernel<<<(B_*MEM_*D_ + 255)/256, 256>>>(seq, out + (size_t)B_*D_);
}

// round 17
// speedup vs baseline: 2.6399x; 2.6399x over previous
#include <cuda_runtime.h>
#include <cuda_fp16.h>
#include <math.h>
#include <stdint.h>

#define B_    2048
#define D_    1024
#define H_    8
#define F_    4096
#define L_    2
#define MEM_  16
#define ACT_  32
#define STO_  1024
#define HID_  1024
#define HD_   128
#define S_    17
#define BS_   (B_*S_)
#define TOKK_ 1088
#define RELW_ 513
#define SCALE_ 0.08838834764831845f
#define EPS_  1e-4f

typedef __half fp16;

// ---- scratch ----
__device__ __align__(256) float g_seq[BS_*D_];
__device__ __align__(256) fp16  g_xn[BS_*D_];
__device__ __align__(256) float g_q[BS_*D_];
__device__ __align__(256) float g_k[BS_*D_];
__device__ __align__(256) float g_v[BS_*D_];
__device__ __align__(256) fp16  g_att[BS_*D_];
__device__ __align__(256) fp16  g_ffh[(size_t)BS_*F_];
__device__ __align__(256) float g_h1[B_*HID_];
__device__ __align__(256) fp16  g_h2[B_*HID_];
__device__ __align__(256) fp16  g_tok[B_*TOKK_];

#define SZ_SQ   (1024ull*1024ull)
#define OFF_W1T 0ull
#define SZ_W1T  (1024ull*1088ull)
#define OFF_W2T (OFF_W1T + SZ_W1T)
#define OFF_LYR(l) (OFF_W2T + SZ_SQ + (unsigned long long)(l)*12ull*SZ_SQ)
#define OFF_Q(l)  (OFF_LYR(l))
#define OFF_K(l)  (OFF_LYR(l) + 1ull*SZ_SQ)
#define OFF_V(l)  (OFF_LYR(l) + 2ull*SZ_SQ)
#define OFF_O(l)  (OFF_LYR(l) + 3ull*SZ_SQ)
#define OFF_F1(l) (OFF_LYR(l) + 4ull*SZ_SQ)
#define OFF_F2(l) (OFF_LYR(l) + 8ull*SZ_SQ)
#define WT_TOTAL  (OFF_W2T + SZ_SQ + 2ull*12ull*SZ_SQ)
__device__ __align__(256) fp16 g_wt[WT_TOTAL];

// ---- helpers ----
__device__ __forceinline__ uint32_t s2u(const void* p){
    uint32_t a;
    asm("{ .reg .u64 t; cvta.to.shared.u64 t, %1; cvt.u32.u64 %0, t; }" : "=r"(a) : "l"(p));
    return a;
}
__device__ __forceinline__ void cp16(uint32_t d, const void* s){
    asm volatile("cp.async.cg.shared.global [%0], [%1], 16;" :: "r"(d), "l"(s));
}
__device__ __forceinline__ void ldsm4(uint32_t* r, uint32_t a){
    asm volatile("ldmatrix.sync.aligned.m8n8.x4.shared.b16 {%0,%1,%2,%3}, [%4];"
        : "=r"(r[0]),"=r"(r[1]),"=r"(r[2]),"=r"(r[3]) : "r"(a));
}
__device__ __forceinline__ void mma16816(float* d, const uint32_t* a, const uint32_t* b){
    asm volatile("mma.sync.aligned.m16n8k16.row.col.f32.f16.f16.f32 "
        "{%0,%1,%2,%3}, {%4,%5,%6,%7}, {%8,%9}, {%0,%1,%2,%3};"
        : "+f"(d[0]),"+f"(d[1]),"+f"(d[2]),"+f"(d[3])
        : "r"(a[0]),"r"(a[1]),"r"(a[2]),"r"(a[3]), "r"(b[0]),"r"(b[1]));
}
__device__ __forceinline__ float gelu_exact(float x){
    return 0.5f * x * (1.0f + erff(x * 0.70710678118654752f));
}

// ---- GEMM: C[M,N] = A[M,K] @ B[N,K]^T + bias; mma.sync fp16 single-pass, fp32 accum ----
// EPI: 0 bias->Cf; 1 bias+gelu->Ch (fp16); 2 bias+residual(Cf)->Cf
// Stage: K=32. A/B tiles 128rows x 32cols fp16, padded row stride 80B. 2 tiles = 20480B/stage.
#define STG_B   20480
#define GEMM_SMEM (4*STG_B)

template<int EPI>
__global__ void __launch_bounds__(256, 2) gemm_f16(
    const fp16* __restrict__ A, const fp16* __restrict__ Bw,
    const float* __restrict__ bias, float* __restrict__ Cf,
    fp16* __restrict__ Ch, int N, int K, int nstages)
{
    extern __shared__ __align__(128) char sm_[];
    uint32_t sb = s2u(sm_);
    const int tid = threadIdx.x;
    const int wid = tid >> 5, lane = tid & 31;
    const int warp_m = wid & 3, warp_n = wid >> 2;     // 4 x 2 warps
    const int m0 = blockIdx.y * 128, n0 = blockIdx.x * 128;

    const size_t rowK = (size_t)K * 2;
    const char* pA = (const char*)A  + (size_t)m0 * rowK;
    const char* pB = (const char*)Bw + (size_t)n0 * rowK;

    auto load_stage = [&](int ks, int buf){
        uint32_t base = sb + buf * STG_B;
        size_t kb = (size_t)ks * 64;                    // 32 fp16 = 64 bytes
        #pragma unroll
        for (int t = 0; t < 2; t++){
            int idx = tid + t * 256;                    // 0..511
            int r = idx >> 2, c = idx & 3;
            uint32_t doff = r * 80 + c * 16;
            size_t go = (size_t)r * rowK + kb + c * 16;
            cp16(base + doff,         pA + go);
            cp16(base + 10240 + doff, pB + go);
        }
        asm volatile("cp.async.commit_group;" ::: "memory");
    };

    int npro = nstages < 3 ? nstages : 3;
    for (int i = 0; i < npro; i++) load_stage(i, i);

    float acc[2][8][4];
    #pragma unroll
    for (int mt = 0; mt < 2; mt++)
        #pragma unroll
        for (int nf = 0; nf < 8; nf++)
            #pragma unroll
            for (int i = 0; i < 4; i++) acc[mt][nf][i] = 0.f;

    const uint32_t aoff = (warp_m * 32 + (lane & 15)) * 80 + (lane >> 4) * 16;
    const uint32_t boff = (warp_n * 64 + (lane & 15)) * 80 + ((lane >> 4) & 1) * 16;

    for (int s = 0; s < nstages; s++){
        int rem = nstages - 1 - s;
        if (rem >= 2)      asm volatile("cp.async.wait_group 2;" ::: "memory");
        else if (rem == 1) asm volatile("cp.async.wait_group 1;" ::: "memory");
        else               asm volatile("cp.async.wait_group 0;" ::: "memory");
        __syncthreads();
        if (s + 3 < nstages) load_stage(s + 3, (s + 3) & 3);

        uint32_t base = sb + (s & 3) * STG_B;
        #pragma unroll
        for (int ks = 0; ks < 2; ks++){
            uint32_t ah[2][4], bh[8][2];
            #pragma unroll
            for (int mt = 0; mt < 2; mt++)
                ldsm4(ah[mt], base + aoff + mt * (16 * 80) + ks * 32);
            #pragma unroll
            for (int fp = 0; fp < 4; fp++){
                uint32_t tt[4];
                ldsm4(tt, base + 10240 + boff + fp * (16 * 80) + ks * 32);
                bh[2*fp][0] = tt[0]; bh[2*fp+1][0] = tt[1];
                bh[2*fp][1] = tt[2]; bh[2*fp+1][1] = tt[3];
            }
            #pragma unroll
            for (int mt = 0; mt < 2; mt++)
                #pragma unroll
                for (int nf = 0; nf < 8; nf++)
                    mma16816(acc[mt][nf], ah[mt], bh[nf]);
        }
    }

    // ---- epilogue ----
    const int g = lane >> 2, tig = lane & 3;
    #pragma unroll
    for (int mt = 0; mt < 2; mt++){
        int r0 = m0 + warp_m * 32 + mt * 16 + g;
        #pragma unroll
        for (int nf = 0; nf < 8; nf++){
            int j0 = n0 + warp_n * 64 + nf * 8 + 2 * tig;
            float b0 = bias[j0], b1 = bias[j0 + 1];
            float v00 = acc[mt][nf][0] + b0, v01 = acc[mt][nf][1] + b1;
            float v10 = acc[mt][nf][2] + b0, v11 = acc[mt][nf][3] + b1;
            size_t o0 = (size_t)r0 * N + j0;
            size_t o1 = (size_t)(r0 + 8) * N + j0;
            if (EPI == 0){
                float2 w0 = {v00, v01}, w1 = {v10, v11};
                *(float2*)&Cf[o0] = w0;
                *(float2*)&Cf[o1] = w1;
            } else if (EPI == 2){
                float2 r0v = *(const float2*)&Cf[o0];
                float2 r1v = *(const float2*)&Cf[o1];
                float2 w0 = {v00 + r0v.x, v01 + r0v.y};
                float2 w1 = {v10 + r1v.x, v11 + r1v.y};
                *(float2*)&Cf[o0] = w0;
                *(float2*)&Cf[o1] = w1;
            } else {
                v00 = gelu_exact(v00); v01 = gelu_exact(v01);
                v10 = gelu_exact(v10); v11 = gelu_exact(v11);
                *(__half2*)(Ch + o0) = __floats2half2_rn(v00, v01);
                *(__half2*)(Ch + o1) = __floats2half2_rn(v10, v11);
            }
        }
    }
}

// ---- weight transpose: W[K,N] f32 -> T[N,Kpad] fp16 ----
__global__ void transpose_cvt(const float* __restrict__ W, fp16* __restrict__ T,
                              int K, int N, int Kpad)
{
    __shared__ float t[32][33];
    int n0 = blockIdx.x * 32, k0 = blockIdx.y * 32;
    int tx = threadIdx.x, ty = threadIdx.y;
    #pragma unroll
    for (int i = 0; i < 4; i++){
        int k = k0 + ty + i * 8;
        t[ty + i * 8][tx] = (k < K) ? W[(size_t)k * N + n0 + tx] : 0.f;
    }
    __syncthreads();
    #pragma unroll
    for (int i = 0; i < 4; i++){
        int n = n0 + ty + i * 8;
        int k = k0 + tx;
        T[(size_t)n * Kpad + k] = __float2half_rn(t[tx][ty + i * 8]);
    }
}

__global__ void build_tok(const float* __restrict__ stoch, const float* __restrict__ action,
                          fp16* __restrict__ th)
{
    int idx = blockIdx.x * blockDim.x + threadIdx.x;
    if (idx >= B_ * TOKK_) return;
    int b = idx / TOKK_, c = idx % TOKK_;
    float v = 0.f;
    if (c < STO_) v = stoch[b * STO_ + c];
    else if (c < STO_ + ACT_){
        float a = action[b * ACT_ + (c - STO_)];
        v = a / fmaxf(fabsf(a), 1.0f);
    }
    th[idx] = __float2half_rn(v);
}

__global__ void build_seq(const float* __restrict__ memory, const float* __restrict__ tok,
                          float* __restrict__ seq)
{
    int idx = blockIdx.x * blockDim.x + threadIdx.x;
    if (idx >= BS_ * D_) return;
    int b = idx / (S_ * D_);
    int r = idx % (S_ * D_);
    int s = r / D_, d = r % D_;
    seq[idx] = (s < MEM_) ? memory[((size_t)b * MEM_ + s) * D_ + d]
                          : tok[(size_t)b * D_ + d];
}

__global__ void rmsnorm_h(const float* __restrict__ x, const float* __restrict__ w,
                          fp16* __restrict__ y, int apply_silu)
{
    __shared__ float red[8];
    int row = blockIdx.x, tid = threadIdx.x;
    float4 v = ((const float4*)(x + (size_t)row * 1024))[tid];
    float ss = v.x*v.x + v.y*v.y + v.z*v.z + v.w*v.w;
    #pragma unroll
    for (int o = 16; o; o >>= 1) ss += __shfl_xor_sync(0xffffffffu, ss, o);
    if ((tid & 31) == 0) red[tid >> 5] = ss;
    __syncthreads();
    float tot = 0.f;
    #pragma unroll
    for (int i = 0; i < 8; i++) tot += red[i];
    float inv = rsqrtf(tot * (1.0f/1024.0f) + EPS_);
    float4 wv = ((const float4*)w)[tid];
    float o0 = v.x*inv*wv.x, o1 = v.y*inv*wv.y, o2 = v.z*inv*wv.z, o3 = v.w*inv*wv.w;
    if (apply_silu){
        o0 /= (1.f + expf(-o0)); o1 /= (1.f + expf(-o1));
        o2 /= (1.f + expf(-o2)); o3 /= (1.f + expf(-o3));
    }
    size_t off = (size_t)row * 1024 + tid * 4;
    *(__half2*)(y + off)     = __floats2half2_rn(o0, o1);
    *(__half2*)(y + off + 2) = __floats2half2_rn(o2, o3);
}

__global__ void __launch_bounds__(256) attention_kernel(
    const float* __restrict__ q, const float* __restrict__ k,
    const float* __restrict__ v, const float* __restrict__ rel_l,
    fp16* __restrict__ att)
{
    __shared__ __align__(16) float sv[S_][132];
    __shared__ float sq[S_][129];
    __shared__ float sk[S_][129];
    int bh = blockIdx.x;
    int b = bh >> 3, h = bh & 7;
    int tid = threadIdx.x;
    for (int idx = tid; idx < S_ * HD_; idx += 256){
        int s = idx / HD_, d = idx % HD_;
        size_t g = ((size_t)(b * S_ + s)) * D_ + h * HD_ + d;
        sq[s][d] = q[g]; sk[s][d] = k[g]; sv[s][d] = v[g];
    }
    __syncthreads();
    int warp = tid >> 5, lane = tid & 31;
    for (int qs = warp; qs < S_; qs += 8){
        float score = -1e30f;
        if (lane < S_){
            float s = 0.f;
            #pragma unroll 8
            for (int d = 0; d < HD_; d++) s += sq[qs][d] * sk[lane][d];
            score = s * SCALE_ + rel_l[(qs - lane + 256) * H_ + h];
        }
        float m = score;
        #pragma unroll
        for (int o = 16; o; o >>= 1) m = fmaxf(m, __shfl_xor_sync(0xffffffffu, m, o));
        float p = (lane < S_) ? expf(score - m) : 0.f;
        float sum = p;
        #pragma unroll
        for (int o = 16; o; o >>= 1) sum += __shfl_xor_sync(0xffffffffu, sum, o);
        p /= sum;
        float a0 = 0.f, a1 = 0.f, a2 = 0.f, a3 = 0.f;
        #pragma unroll
        for (int ks = 0; ks < S_; ks++){
            float pk = __shfl_sync(0xffffffffu, p, ks);
            float4 vv = *(const float4*)&sv[ks][lane * 4];
            a0 += pk * vv.x; a1 += pk * vv.y; a2 += pk * vv.z; a3 += pk * vv.w;
        }
        size_t o = ((size_t)(b * S_ + qs)) * D_ + h * HD_ + lane * 4;
        *(__half2*)(att + o)     = __floats2half2_rn(a0, a1);
        *(__half2*)(att + o + 2) = __floats2half2_rn(a2, a3);
    }
}

__global__ void final_deter_kernel(const float* __restrict__ seq, const float* __restrict__ deter,
                                   const float* __restrict__ fnw, float* __restrict__ out)
{
    __shared__ float red[8];
    int b = blockIdx.x, tid = threadIdx.x;
    float4 x  = ((const float4*)(seq + ((size_t)(b * S_ + S_ - 1)) * D_))[tid];
    float4 dd = ((const float4*)(deter + (size_t)b * D_))[tid];
    float4 t = {x.x + dd.x, x.y + dd.y, x.z + dd.z, x.w + dd.w};
    float ss = t.x*t.x + t.y*t.y + t.z*t.z + t.w*t.w;
    #pragma unroll
    for (int o = 16; o; o >>= 1) ss += __shfl_xor_sync(0xffffffffu, ss, o);
    if ((tid & 31) == 0) red[tid >> 5] = ss;
    __syncthreads();
    float tot = 0.f;
    #pragma unroll
    for (int i = 0; i < 8; i++) tot += red[i];
    float inv = rsqrtf(tot * (1.0f/1024.0f) + EPS_);
    float4 w = ((const float4*)fnw)[tid];
    float4 o = {t.x*inv*w.x, t.y*inv*w.y, t.z*inv*w.z, t.w*inv*w.w};
    ((float4*)(out + (size_t)b * D_))[tid] = o;
}

__global__ void copy_mem_kernel(const float* __restrict__ seq, float* __restrict__ out)
{
    int idx = blockIdx.x * blockDim.x + threadIdx.x;
    if (idx >= B_ * MEM_ * D_) return;
    int b = idx / (MEM_ * D_);
    int r = idx % (MEM_ * D_);
    out[idx] = seq[((size_t)b * S_ + 1) * D_ + r];
}

extern "C" void kernel_launch(void* const* d_in, const int* in_sizes, int n_in,
                              void* d_out, int out_size)
{
    const float* stoch   = (const float*)d_in[0];
    const float* deter   = (const float*)d_in[1];
    const float* action  = (const float*)d_in[2];
    const float* memory  = (const float*)d_in[3];
    const float* inp_w1  = (const float*)d_in[4];
    const float* inp_b1  = (const float*)d_in[5];
    const float* inp_nw  = (const float*)d_in[6];
    const float* inp_w2  = (const float*)d_in[7];
    const float* inp_b2  = (const float*)d_in[8];
    const float* Wq      = (const float*)d_in[9];
    const float* bq      = (const float*)d_in[10];
    const float* Wk      = (const float*)d_in[11];
    const float* bk      = (const float*)d_in[12];
    const float* Wv      = (const float*)d_in[13];
    const float* bv      = (const float*)d_in[14];
    const float* Wo      = (const float*)d_in[15];
    const float* bo      = (const float*)d_in[16];
    const float* rel_emb = (const float*)d_in[17];
    const float* n1w     = (const float*)d_in[18];
    const float* n2w     = (const float*)d_in[19];
    const float* ffw1    = (const float*)d_in[20];
    const float* ffb1    = (const float*)d_in[21];
    const float* ffw2    = (const float*)d_in[22];
    const float* ffb2    = (const float*)d_in[23];
    const float* fnw     = (const float*)d_in[24];
    float* out = (float*)d_out;

    float *seq, *q, *k, *v, *h1;
    fp16 *xn, *att, *ffh, *h2, *tok, *wt;
    cudaGetSymbolAddress((void**)&seq, g_seq);
    cudaGetSymbolAddress((void**)&xn,  g_xn);
    cudaGetSymbolAddress((void**)&q,   g_q);
    cudaGetSymbolAddress((void**)&k,   g_k);
    cudaGetSymbolAddress((void**)&v,   g_v);
    cudaGetSymbolAddress((void**)&att, g_att);
    cudaGetSymbolAddress((void**)&ffh, g_ffh);
    cudaGetSymbolAddress((void**)&h1,  g_h1);
    cudaGetSymbolAddress((void**)&h2,  g_h2);
    cudaGetSymbolAddress((void**)&tok, g_tok);
    cudaGetSymbolAddress((void**)&wt,  g_wt);

    cudaFuncSetAttribute(gemm_f16<0>, cudaFuncAttributeMaxDynamicSharedMemorySize, GEMM_SMEM);
    cudaFuncSetAttribute(gemm_f16<1>, cudaFuncAttributeMaxDynamicSharedMemorySize, GEMM_SMEM);
    cudaFuncSetAttribute(gemm_f16<2>, cudaFuncAttributeMaxDynamicSharedMemorySize, GEMM_SMEM);

    dim3 tb(32, 8);
    transpose_cvt<<<dim3(32, 34), tb>>>(inp_w1, wt + OFF_W1T, 1056, 1024, 1088);
    transpose_cvt<<<dim3(32, 32), tb>>>(inp_w2, wt + OFF_W2T, 1024, 1024, 1024);
    for (int l = 0; l < L_; l++){
        transpose_cvt<<<dim3(32, 32), tb>>>(Wq + (size_t)l*D_*D_,   wt + OFF_Q(l),  1024, 1024, 1024);
        transpose_cvt<<<dim3(32, 32), tb>>>(Wk + (size_t)l*D_*D_,   wt + OFF_K(l),  1024, 1024, 1024);
        transpose_cvt<<<dim3(32, 32), tb>>>(Wv + (size_t)l*D_*D_,   wt + OFF_V(l),  1024, 1024, 1024);
        transpose_cvt<<<dim3(32, 32), tb>>>(Wo + (size_t)l*D_*D_,   wt + OFF_O(l),  1024, 1024, 1024);
        transpose_cvt<<<dim3(128, 32), tb>>>(ffw1 + (size_t)l*D_*F_, wt + OFF_F1(l), 1024, 4096, 1024);
        transpose_cvt<<<dim3(32, 128), tb>>>(ffw2 + (size_t)l*F_*D_, wt + OFF_F2(l), 4096, 1024, 4096);
    }

    build_tok<<<(B_*TOKK_ + 255)/256, 256>>>(stoch, action, tok);
    gemm_f16<0><<<dim3(8, 16), 256, GEMM_SMEM>>>(tok, wt + OFF_W1T, inp_b1, h1, nullptr, 1024, 1088, 34);
    rmsnorm_h<<<B_, 256>>>(h1, inp_nw, h2, 1);
    gemm_f16<0><<<dim3(8, 16), 256, GEMM_SMEM>>>(h2, wt + OFF_W2T, inp_b2, h1, nullptr, 1024, 1024, 32);
    build_seq<<<(BS_*D_ + 255)/256, 256>>>(memory, h1, seq);

    for (int l = 0; l < L_; l++){
        rmsnorm_h<<<BS_, 256>>>(seq, n1w + l*D_, xn, 0);
        gemm_f16<0><<<dim3(8, 272), 256, GEMM_SMEM>>>(xn, wt + OFF_Q(l), bq + l*D_, q, nullptr, 1024, 1024, 32);
        gemm_f16<0><<<dim3(8, 272), 256, GEMM_SMEM>>>(xn, wt + OFF_K(l), bk + l*D_, k, nullptr, 1024, 1024, 32);
        gemm_f16<0><<<dim3(8, 272), 256, GEMM_SMEM>>>(xn, wt + OFF_V(l), bv + l*D_, v, nullptr, 1024, 1024, 32);
        attention_kernel<<<B_*H_, 256>>>(q, k, v, rel_emb + (size_t)l*RELW_*H_, att);
        gemm_f16<2><<<dim3(8, 272), 256, GEMM_SMEM>>>(att, wt + OFF_O(l), bo + l*D_, seq, nullptr, 1024, 1024, 32);
        rmsnorm_h<<<BS_, 256>>>(seq, n2w + l*D_, xn, 0);
        gemm_f16<1><<<dim3(32, 272), 256, GEMM_SMEM>>>(xn, wt + OFF_F1(l), ffb1 + l*F_, nullptr, ffh, 4096, 1024, 32);
        gemm_f16<2><<<dim3(8, 272), 256, GEMM_SMEM>>>(ffh, wt + OFF_F2(l), ffb2 + l*D_, seq, nullptr, 1024, 4096, 128);
    }

    final_deter_kernel<<<B_, 256>>>(seq, deter, fnw, out);
    copy_mem_kernel<<<(B_*MEM_*D_ + 255)/256, 256>>>(seq, out + (size_t)B_*D_);
}